// round 1
// baseline (speedup 1.0000x reference)
#include <cuda_runtime.h>

#define IN_CH   32
#define OUT_CH  32
#define NODES   24
#define DIM     768            // 24 * 32
#define ROWS    128            // batch rows per CTA
#define THREADS 256

typedef unsigned long long ull;

// xs2: duplicated x pairs (v,v), one ull per (row,k). pitch 65 ulls so that
// row-groups 4 apart land in distinct bank groups (4*65*8 = 2080 B, 2080/4 % 32 = 8).
#define XPITCH   65
#define XS2_ULLS (ROWS * XPITCH)                    // 8320 ulls = 66560 B
#define WS_FLOATS (64 * 32)                          // 8192 B
#define SMEM_BYTES (XS2_ULLS * 8 + WS_FLOATS * 4)    // 74752 B

__device__ __forceinline__ ull ffma2(ull a, ull b, ull c) {
    ull d;
    asm("fma.rn.f32x2 %0, %1, %2, %3;" : "=l"(d) : "l"(a), "l"(b), "l"(c));
    return d;
}
__device__ __forceinline__ ull pack_dup(float v) {
    ull d;
    asm("mov.b64 %0, {%1, %1};" : "=l"(d) : "f"(v));
    return d;
}
__device__ __forceinline__ ull pack2(float a, float b) {
    ull d;
    asm("mov.b64 %0, {%1, %2};" : "=l"(d) : "f"(a), "f"(b));
    return d;
}
__device__ __forceinline__ float2 unpack2(ull v) {
    float2 f;
    asm("mov.b64 {%0, %1}, %2;" : "=f"(f.x), "=f"(f.y) : "l"(v));
    return f;
}

__global__ __launch_bounds__(THREADS, 2)
void skel_linear_kernel(const float* __restrict__ x,
                        const float* __restrict__ weight,
                        const float* __restrict__ bias,
                        float* __restrict__ out,
                        int batch)
{
    extern __shared__ __align__(16) char smem_raw[];
    ull*   xs2 = reinterpret_cast<ull*>(smem_raw);
    float* ws  = reinterpret_cast<float*>(smem_raw + XS2_ULLS * 8);

    const int d    = blockIdx.y;               // output node
    const int row0 = blockIdx.x * ROWS;        // batch row tile
    const int tid  = threadIdx.x;

    // Input columns used by node d: block (d-1) then block d. For d==0 only
    // block 0 is valid; the k>=32 weights are zeroed (mask semantics).
    const int col_base = (d > 0 ? d - 1 : 0) * IN_CH;

    // --- load weights: ws[k][c]  (k = local input col 0..63, c = output col 0..31)
    for (int i = tid; i < 64 * 32; i += THREADS) {
        int k = i >> 5, c = i & 31;
        float w = 0.0f;
        if (d > 0 || k < 32)
            w = weight[(size_t)(d * OUT_CH + c) * DIM + col_base + k];
        ws[i] = w;
    }

    // --- load x tile (128 rows x 64 cols), duplicating each value into an f32x2 pair
    {
        const int k4 = tid & 15;        // 16 float4 per row
        const int r  = tid >> 4;        // 16 rows per pass
        #pragma unroll
        for (int rr = r; rr < ROWS; rr += 16) {
            const float4 v = *reinterpret_cast<const float4*>(
                x + (size_t)(row0 + rr) * DIM + col_base + k4 * 4);
            ull* dst = &xs2[rr * XPITCH + k4 * 4];
            dst[0] = pack_dup(v.x);
            dst[1] = pack_dup(v.y);
            dst[2] = pack_dup(v.z);
            dst[3] = pack_dup(v.w);
        }
    }
    __syncthreads();

    // --- compute: thread tile = 4 rows x 4 cols (as 2 column-pairs)
    const int cg = tid & 7;    // column group: cols 4*cg .. 4*cg+3
    const int rg = tid >> 3;   // row group:    rows 4*rg .. 4*rg+3
    const int r0 = rg * 4;

    // init accumulators with bias pairs (same for all rows)
    const int ocol = d * OUT_CH + cg * 4;
    const ull bp0 = pack2(bias[ocol + 0], bias[ocol + 1]);
    const ull bp1 = pack2(bias[ocol + 2], bias[ocol + 3]);
    ull acc[8];
    #pragma unroll
    for (int rr = 0; rr < 4; ++rr) { acc[rr * 2] = bp0; acc[rr * 2 + 1] = bp1; }

    const ull* wp = reinterpret_cast<const ull*>(ws);   // wp[k*16 + pair]
    #pragma unroll 8
    for (int k = 0; k < 64; ++k) {
        const ull w0 = wp[k * 16 + cg * 2 + 0];
        const ull w1 = wp[k * 16 + cg * 2 + 1];
        #pragma unroll
        for (int rr = 0; rr < 4; ++rr) {
            const ull xp = xs2[(r0 + rr) * XPITCH + k];
            acc[rr * 2 + 0] = ffma2(xp, w0, acc[rr * 2 + 0]);
            acc[rr * 2 + 1] = ffma2(xp, w1, acc[rr * 2 + 1]);
        }
    }

    // --- store 4 rows x 4 cols (float4, 16B aligned: ocol % 4 == 0)
    #pragma unroll
    for (int rr = 0; rr < 4; ++rr) {
        const float2 a0 = unpack2(acc[rr * 2 + 0]);
        const float2 a1 = unpack2(acc[rr * 2 + 1]);
        float4 v = make_float4(a0.x, a0.y, a1.x, a1.y);
        *reinterpret_cast<float4*>(out + (size_t)(row0 + r0 + rr) * DIM + ocol) = v;
    }
}

extern "C" void kernel_launch(void* const* d_in, const int* in_sizes, int n_in,
                              void* d_out, int out_size)
{
    const float* x      = (const float*)d_in[0];
    const float* weight = (const float*)d_in[1];
    const float* bias   = (const float*)d_in[2];
    // d_in[3] = mask: structure is fixed (self-loops + chain); applied implicitly.
    float* out = (float*)d_out;

    const int batch = in_sizes[0] / DIM;   // 32768

    cudaFuncSetAttribute(skel_linear_kernel,
                         cudaFuncAttributeMaxDynamicSharedMemorySize, SMEM_BYTES);

    dim3 grid(batch / ROWS, NODES, 1);     // (256, 24)
    skel_linear_kernel<<<grid, THREADS, SMEM_BYTES>>>(x, weight, bias, out, batch);
}

// round 2
// speedup vs baseline: 1.8192x; 1.8192x over previous
#include <cuda_runtime.h>

#define NODES   24
#define DIM     768
#define ROWS    512            // batch rows per CTA
#define THREADS 256
#define CK      16             // k-chunk
#define NC      4              // 64 k total / CK
#define XSTR    20             // x smem row stride in floats (16B-aligned, conflict-free)
#define XBUF    (ROWS * XSTR)  // floats per x buffer = 10240
#define WSTR    36             // w smem row stride in floats (16B-aligned, <=4-way store conflict)
#define SMEM_FLOATS (2 * XBUF + 64 * WSTR)
#define SMEM_BYTES  (SMEM_FLOATS * 4)   // 91,136 B

typedef unsigned long long ull;

__device__ __forceinline__ ull ffma2(ull a, ull b, ull c) {
    ull d;
    asm("fma.rn.f32x2 %0, %1, %2, %3;" : "=l"(d) : "l"(a), "l"(b), "l"(c));
    return d;
}
__device__ __forceinline__ ull pack_dup(float v) {
    ull d;
    asm("mov.b64 %0, {%1, %1};" : "=l"(d) : "f"(v));
    return d;
}
__device__ __forceinline__ ull pack2(float a, float b) {
    ull d;
    asm("mov.b64 %0, {%1, %2};" : "=l"(d) : "f"(a), "f"(b));
    return d;
}
__device__ __forceinline__ float2 unpack2(ull v) {
    float2 f;
    asm("mov.b64 {%0, %1}, %2;" : "=f"(f.x), "=f"(f.y) : "l"(v));
    return f;
}
__device__ __forceinline__ void cp16(unsigned saddr, const void* gaddr) {
    asm volatile("cp.async.cg.shared.global [%0], [%1], 16;" :: "r"(saddr), "l"(gaddr));
}

__global__ __launch_bounds__(THREADS, 2)
void skel_linear2(const float* __restrict__ x,
                  const float* __restrict__ weight,
                  const float* __restrict__ bias,
                  float* __restrict__ out)
{
    extern __shared__ __align__(16) float sm[];
    float* xs = sm;                      // [2][ROWS][XSTR]  (k within row: 0..CK-1)
    float* ws = sm + 2 * XBUF;           // [64][WSTR], cols 0..31 valid

    const int tid  = threadIdx.x;
    const int d    = blockIdx.y;
    const int row0 = blockIdx.x * ROWS;
    const int cb   = (d > 0 ? d - 1 : 0) * 32;   // input col base (blocks d-1, d)

    const int cg  = tid & 3;    // column group: cols 8*cg .. 8*cg+7
    const int rid = tid >> 2;   // 0..63; thread rows: rid + 64*rr, rr=0..7

    unsigned sbase;
    asm("{ .reg .u64 t; cvta.to.shared.u64 t, %1; cvt.u32.u64 %0, t; }"
        : "=r"(sbase) : "l"(sm));

    // ---- load weights (coalesced over k), zero masked region for d==0 ----
    {
        const int c0 = tid >> 6;          // 0..3
        const int k  = tid & 63;
        #pragma unroll
        for (int i = 0; i < 8; ++i) {
            const int c = c0 + i * 4;
            float v = 0.0f;
            if (d > 0 || k < 32)
                v = weight[(size_t)(d * 32 + c) * DIM + cb + k];
            ws[k * WSTR + c] = v;
        }
    }

    // ---- async x-chunk prefetch (double buffered) ----
    const float* gx0 = x + (size_t)(row0 + rid) * DIM + cb + cg * 4;
    const unsigned sx0 = sbase + (rid * XSTR + cg * 4) * 4;

    // prefetch chunk 0 -> buf 0
    {
        const float* gp = gx0;                 // + 0*CK
        #pragma unroll
        for (int i = 0; i < 8; ++i)
            cp16(sx0 + (unsigned)(i * 64 * XSTR * 4), gp + (size_t)i * 64 * DIM);
        asm volatile("cp.async.commit_group;");
    }

    // ---- accumulators init with bias ----
    ull acc[8][4];
    {
        const float* bp = bias + d * 32 + cg * 8;
        const ull b0 = pack2(bp[0], bp[1]);
        const ull b1 = pack2(bp[2], bp[3]);
        const ull b2 = pack2(bp[4], bp[5]);
        const ull b3 = pack2(bp[6], bp[7]);
        #pragma unroll
        for (int rr = 0; rr < 8; ++rr) {
            acc[rr][0] = b0; acc[rr][1] = b1; acc[rr][2] = b2; acc[rr][3] = b3;
        }
    }

    // ---- main loop over k-chunks ----
    for (int ck = 0; ck < NC; ++ck) {
        if (ck < NC - 1) {
            const int nb = (ck + 1) & 1;
            const float* gp = gx0 + (ck + 1) * CK;
            const unsigned sp = sx0 + (unsigned)(nb * XBUF * 4);
            #pragma unroll
            for (int i = 0; i < 8; ++i)
                cp16(sp + (unsigned)(i * 64 * XSTR * 4), gp + (size_t)i * 64 * DIM);
            asm volatile("cp.async.commit_group;");
            asm volatile("cp.async.wait_group 1;");
        } else {
            asm volatile("cp.async.wait_group 0;");
        }
        __syncthreads();

        const float* xb = xs + (ck & 1) * XBUF + rid * XSTR;
        const float* wb = ws + ck * CK * WSTR + cg * 8;

        #pragma unroll
        for (int k = 0; k < CK; ++k) {
            ull xp[8];
            #pragma unroll
            for (int rr = 0; rr < 8; ++rr)
                xp[rr] = pack_dup(xb[rr * 64 * XSTR + k]);

            const float* wrow = wb + k * WSTR;
            const ull w0 = ((const ull*)wrow)[0];
            const ull w1 = ((const ull*)wrow)[1];
            const ull w2 = ((const ull*)wrow)[2];
            const ull w3 = ((const ull*)wrow)[3];

            #pragma unroll
            for (int rr = 0; rr < 8; ++rr) {
                acc[rr][0] = ffma2(xp[rr], w0, acc[rr][0]);
                acc[rr][1] = ffma2(xp[rr], w1, acc[rr][1]);
                acc[rr][2] = ffma2(xp[rr], w2, acc[rr][2]);
                acc[rr][3] = ffma2(xp[rr], w3, acc[rr][3]);
            }
        }
        __syncthreads();
    }

    // ---- store 8 rows x 8 cols ----
    float* op = out + (size_t)(row0 + rid) * DIM + d * 32 + cg * 8;
    #pragma unroll
    for (int rr = 0; rr < 8; ++rr) {
        const float2 a0 = unpack2(acc[rr][0]);
        const float2 a1 = unpack2(acc[rr][1]);
        const float2 a2 = unpack2(acc[rr][2]);
        const float2 a3 = unpack2(acc[rr][3]);
        float* o = op + (size_t)rr * 64 * DIM;
        *reinterpret_cast<float4*>(o)     = make_float4(a0.x, a0.y, a1.x, a1.y);
        *reinterpret_cast<float4*>(o + 4) = make_float4(a2.x, a2.y, a3.x, a3.y);
    }
}

extern "C" void kernel_launch(void* const* d_in, const int* in_sizes, int n_in,
                              void* d_out, int out_size)
{
    const float* x      = (const float*)d_in[0];
    const float* weight = (const float*)d_in[1];
    const float* bias   = (const float*)d_in[2];
    // d_in[3] = mask: fixed structure (self-loops + chain), applied implicitly.
    float* out = (float*)d_out;

    const int batch = in_sizes[0] / DIM;   // 32768

    cudaFuncSetAttribute(skel_linear2,
                         cudaFuncAttributeMaxDynamicSharedMemorySize, SMEM_BYTES);

    dim3 grid(batch / ROWS, NODES, 1);     // (64, 24)
    skel_linear2<<<grid, THREADS, SMEM_BYTES>>>(x, weight, bias, out);
}

// round 4
// speedup vs baseline: 2.6461x; 1.4545x over previous
#include <cuda_runtime.h>
#include <cuda_bf16.h>
#include <cstdint>

#define NODES 24
#define DIM   768
#define ROWS  128
#define THREADS 256

// smem byte layout (dynamic):
//  x ring: 3 slots x { hi[128][40] bf16, lo[128][40] bf16 }  (row stride 80B)
//  w bufs: 2 bufs  x { hi[32][72] bf16, lo[32][72] bf16 }    (row stride 144B)
//  bias:   768 f32
#define XS      0
#define XTILE   10240                 // 128*80
#define XSLOT   (2*XTILE)             // hi+lo = 20480
#define WS      (3*XSLOT)             // 61440
#define WTILE   4608                  // 32*144
#define WBUF    (2*WTILE)             // 9216
#define BIAS_O  (WS + 2*WBUF)         // 79872
#define SMEM_BYTES (BIAS_O + DIM*4)   // 82944

__device__ __forceinline__ unsigned saddr(const void* p) {
    unsigned a;
    asm("{ .reg .u64 t; cvta.to.shared.u64 t, %1; cvt.u32.u64 %0, t; }" : "=r"(a) : "l"(p));
    return a;
}
__device__ __forceinline__ void split2(float x, float y, uint32_t& h, uint32_t& l) {
    __nv_bfloat162 hv = __floats2bfloat162_rn(x, y);
    h = *reinterpret_cast<uint32_t*>(&hv);
    const float rx = x - __low2float(hv);
    const float ry = y - __high2float(hv);
    __nv_bfloat162 lv = __floats2bfloat162_rn(rx, ry);
    l = *reinterpret_cast<uint32_t*>(&lv);
}
__device__ __forceinline__ void split8(const float4& a, const float4& b, uint4& h, uint4& l) {
    split2(a.x, a.y, h.x, l.x);
    split2(a.z, a.w, h.y, l.y);
    split2(b.x, b.y, h.z, l.z);
    split2(b.z, b.w, h.w, l.w);
}
__device__ __forceinline__ void ldm_x4(uint32_t a, uint32_t r[4]) {
    asm volatile("ldmatrix.sync.aligned.m8n8.x4.shared.b16 {%0,%1,%2,%3}, [%4];"
        : "=r"(r[0]), "=r"(r[1]), "=r"(r[2]), "=r"(r[3]) : "r"(a));
}
__device__ __forceinline__ void ldm_x2(uint32_t a, uint32_t r[2]) {
    asm volatile("ldmatrix.sync.aligned.m8n8.x2.shared.b16 {%0,%1}, [%2];"
        : "=r"(r[0]), "=r"(r[1]) : "r"(a));
}
__device__ __forceinline__ void mma_bf16(float c[4], const uint32_t a[4], const uint32_t b[2]) {
    asm volatile("mma.sync.aligned.m16n8k16.row.col.f32.bf16.bf16.f32 "
        "{%0,%1,%2,%3}, {%4,%5,%6,%7}, {%8,%9}, {%0,%1,%2,%3};"
        : "+f"(c[0]), "+f"(c[1]), "+f"(c[2]), "+f"(c[3])
        : "r"(a[0]), "r"(a[1]), "r"(a[2]), "r"(a[3]), "r"(b[0]), "r"(b[1]));
}

__global__ void __launch_bounds__(THREADS, 2)
skel_mma(const float* __restrict__ x, const float* __restrict__ weight,
         const float* __restrict__ bias, float* __restrict__ out)
{
    extern __shared__ __align__(16) char sm[];
    const unsigned sbase = saddr(sm);

    const int tid  = threadIdx.x;
    const int lane = tid & 31;
    const int wid  = tid >> 5;
    const int row0 = blockIdx.x * ROWS;

    const int warpM = wid >> 1;     // 0..3 -> 32 rows each
    const int warpN = wid & 1;      // 0..1 -> 16 cols each

    // x staging coords (per thread): row = tid>>1, half = tid&1 (16 floats)
    const int xrow  = tid >> 1;
    const int xhalf = tid & 1;
    const float* xg_row = x + (size_t)(row0 + xrow) * DIM + xhalf * 16;
    char* xs_row = sm + XS + xrow * 80 + xhalf * 32;   // + slot*XSLOT

    // w staging coords: c = tid>>3 (0..31), k0 = (tid&7)*8
    const int wc = tid >> 3;
    const int wk0 = (tid & 7) * 8;
    char* ws_row = sm + WS + wc * 144 + wk0 * 2;       // + buf*WBUF

    // ---- prologue ----
    // zero x slot 0 (virtual block -1), hi+lo = 20480 B
    {
        uint4 z = make_uint4(0, 0, 0, 0);
        uint4* p = reinterpret_cast<uint4*>(sm + XS);
        for (int i = tid; i < XSLOT / 16; i += THREADS) p[i] = z;
    }
    for (int i = tid; i < DIM; i += THREADS)
        reinterpret_cast<float*>(sm + BIAS_O)[i] = bias[i];

    float4 xr[4];
    float4 wr[2];
    // load block 0 + node-0 weights
    {
        const float* xg = xg_row;            // block 0 cols
        #pragma unroll
        for (int i = 0; i < 4; ++i) xr[i] = *reinterpret_cast<const float4*>(xg + i * 4);
        const int gcol = (wk0 & 31);         // nd==0: junk chunk0 / self chunk1 (A slot0 is zero)
        const float* wg = weight + (size_t)(0 * 32 + wc) * DIM + gcol;
        wr[0] = *reinterpret_cast<const float4*>(wg);
        wr[1] = *reinterpret_cast<const float4*>(wg + 4);
    }
    // STS block0 -> slot 1, w0 -> buf 0
    {
        uint4 h0, l0, h1, l1;
        split8(xr[0], xr[1], h0, l0);
        split8(xr[2], xr[3], h1, l1);
        char* xb = xs_row + 1 * XSLOT;
        reinterpret_cast<uint4*>(xb)[0] = h0;
        reinterpret_cast<uint4*>(xb)[1] = h1;
        reinterpret_cast<uint4*>(xb + XTILE)[0] = l0;
        reinterpret_cast<uint4*>(xb + XTILE)[1] = l1;
        uint4 wh, wl;
        split8(wr[0], wr[1], wh, wl);
        *reinterpret_cast<uint4*>(ws_row) = wh;
        *reinterpret_cast<uint4*>(ws_row + WTILE) = wl;
    }

    // ldmatrix lane offsets
    const uint32_t a_off = (uint32_t)((warpM * 32 + (lane & 15)) * 80 + (lane >> 4) * 16);
    const uint32_t b_off = (uint32_t)((warpN * 16 + (lane & 7)) * 144 + ((lane >> 3) & 1) * 16);
    const int g  = lane >> 2;
    const int tg = lane & 3;

    // ---- node loop ----
    for (int d = 0; d < NODES; ++d) {
        __syncthreads();

        // prefetch block d+1 / weights d+1 (overlaps the mma below)
        const bool pf = (d + 1 < NODES);
        if (pf) {
            const float* xg = xg_row + (d + 1) * 32;
            #pragma unroll
            for (int i = 0; i < 4; ++i) xr[i] = *reinterpret_cast<const float4*>(xg + i * 4);
            const int nd = d + 1;
            const int gcol = (nd - 1) * 32 + wk0;
            const float* wg = weight + (size_t)(nd * 32 + wc) * DIM + gcol;
            wr[0] = *reinterpret_cast<const float4*>(wg);
            wr[1] = *reinterpret_cast<const float4*>(wg + 4);
        }

        // ---- mma for node d ----
        const uint32_t sA0 = sbase + XS + (uint32_t)((d % 3) * XSLOT);        // block d-1
        const uint32_t sA1 = sbase + XS + (uint32_t)(((d + 1) % 3) * XSLOT);  // block d
        const uint32_t sB  = sbase + WS + (uint32_t)((d & 1) * WBUF);

        // acc init with bias
        float c[2][2][4];
        #pragma unroll
        for (int nt = 0; nt < 2; ++nt) {
            const float2 bv = *reinterpret_cast<const float2*>(
                sm + BIAS_O + (d * 32 + warpN * 16 + nt * 8 + 2 * tg) * 4);
            #pragma unroll
            for (int mt = 0; mt < 2; ++mt) {
                c[mt][nt][0] = bv.x; c[mt][nt][1] = bv.y;
                c[mt][nt][2] = bv.x; c[mt][nt][3] = bv.y;
            }
        }

        #pragma unroll
        for (int kt = 0; kt < 4; ++kt) {
            const uint32_t aB = ((kt >> 1) ? sA1 : sA0) + (uint32_t)((kt & 1) * 32) + a_off;
            const uint32_t bB = sB + (uint32_t)(kt * 32) + b_off;
            uint32_t ah[2][4], al[2][4], bh[2][2], bl[2][2];
            #pragma unroll
            for (int mt = 0; mt < 2; ++mt) {
                ldm_x4(aB + mt * (16 * 80), ah[mt]);
                ldm_x4(aB + mt * (16 * 80) + XTILE, al[mt]);
            }
            #pragma unroll
            for (int nt = 0; nt < 2; ++nt) {
                ldm_x2(bB + nt * (8 * 144), bh[nt]);
                ldm_x2(bB + nt * (8 * 144) + WTILE, bl[nt]);
            }
            #pragma unroll
            for (int mt = 0; mt < 2; ++mt)
                #pragma unroll
                for (int nt = 0; nt < 2; ++nt) {
                    mma_bf16(c[mt][nt], ah[mt], bh[nt]);
                    mma_bf16(c[mt][nt], ah[mt], bl[nt]);
                    mma_bf16(c[mt][nt], al[mt], bh[nt]);
                }
        }

        // ---- epilogue ----
        #pragma unroll
        for (int mt = 0; mt < 2; ++mt) {
            const int r0 = row0 + warpM * 32 + mt * 16 + g;
            #pragma unroll
            for (int nt = 0; nt < 2; ++nt) {
                const int cb = d * 32 + warpN * 16 + nt * 8 + 2 * tg;
                *reinterpret_cast<float2*>(out + (size_t)r0 * DIM + cb) =
                    make_float2(c[mt][nt][0], c[mt][nt][1]);
                *reinterpret_cast<float2*>(out + (size_t)(r0 + 8) * DIM + cb) =
                    make_float2(c[mt][nt][2], c[mt][nt][3]);
            }
        }

        // ---- STS prefetched block/weights for next node ----
        // writes slot (d+2)%3 and buf (d+1)&1 — disjoint from everything read this iter
        if (pf) {
            uint4 h0, l0, h1, l1;
            split8(xr[0], xr[1], h0, l0);
            split8(xr[2], xr[3], h1, l1);
            char* xb = xs_row + ((d + 2) % 3) * XSLOT;
            reinterpret_cast<uint4*>(xb)[0] = h0;
            reinterpret_cast<uint4*>(xb)[1] = h1;
            reinterpret_cast<uint4*>(xb + XTILE)[0] = l0;
            reinterpret_cast<uint4*>(xb + XTILE)[1] = l1;
            uint4 wh, wl;
            split8(wr[0], wr[1], wh, wl);
            char* wb = ws_row + ((d + 1) & 1) * WBUF;
            *reinterpret_cast<uint4*>(wb) = wh;
            *reinterpret_cast<uint4*>(wb + WTILE) = wl;
        }
    }
}

extern "C" void kernel_launch(void* const* d_in, const int* in_sizes, int n_in,
                              void* d_out, int out_size)
{
    const float* x      = (const float*)d_in[0];
    const float* weight = (const float*)d_in[1];
    const float* bias   = (const float*)d_in[2];
    // d_in[3] = mask: fixed structure (self-loops + chain), applied implicitly.
    float* out = (float*)d_out;

    const int batch = in_sizes[0] / DIM;      // 32768

    cudaFuncSetAttribute(skel_mma,
                         cudaFuncAttributeMaxDynamicSharedMemorySize, SMEM_BYTES);

    dim3 grid(batch / ROWS, 1, 1);            // 256 CTAs
    skel_mma<<<grid, THREADS, SMEM_BYTES>>>(x, weight, bias, out);
}